// round 4
// baseline (speedup 1.0000x reference)
#include <cuda_runtime.h>

#define NDIM 2048
#define BKS 32                 // strips of 64 rows
#define NG 273                 // 8-step groups; steps 0..2183
#define NEGF (-1.4426950e10f)  // -1e10 in log2 domain
#define L2E 1.4426950408889634f
#define LN2 0.6931471805599453f
#define BLEN 2064

// g_bnd[b][c] = V[64*(b+1), c] (log2 domain); col c produced at step c+126
__device__ __align__(16) float g_bnd[BKS][BLEN];
__device__ int g_prog[BKS * 32];   // [b*32] = # of 8-col chunks published

__global__ void nw_init() {
    if (threadIdx.x < BKS) g_prog[threadIdx.x * 32] = 0;
}

__device__ __forceinline__ float ex2f_(float x) {
    float r; asm("ex2.approx.f32 %0, %1;" : "=f"(r) : "f"(x)); return r;
}
__device__ __forceinline__ float lg2f_(float x) {
    float r; asm("lg2.approx.f32 %0, %1;" : "=f"(r) : "f"(x)); return r;
}
__device__ __forceinline__ int ld_acq(const int* p) {
    int v; asm volatile("ld.acquire.gpu.global.b32 %0, [%1];" : "=r"(v) : "l"(p) : "memory");
    return v;
}
__device__ __forceinline__ void publish(float* dst, int* pp,
                                        float a0, float a1, float a2, float a3,
                                        float a4, float a5, float a6, float a7,
                                        int cnt, int flag) {
    asm volatile(
        "{\n\t"
        ".reg .pred p;\n\t"
        "setp.ne.s32 p, %11, 0;\n\t"
        "@p st.global.v4.f32 [%0], {%2, %3, %4, %5};\n\t"
        "@p st.global.v4.f32 [%0+16], {%6, %7, %8, %9};\n\t"
        "@p st.release.gpu.global.b32 [%1], %10;\n\t"
        "}"
        :: "l"(dst), "l"(pp),
           "f"(a0), "f"(a1), "f"(a2), "f"(a3),
           "f"(a4), "f"(a5), "f"(a6), "f"(a7),
           "r"(cnt), "r"(flag) : "memory");
}

// log2-domain smoothed max. up/dg are EARLY (old data via shfl/window);
// lf is LATE (previous step's own result) -> chain from lf is minimal.
__device__ __forceinline__ float lse2(float up, float dg, float lf,
                                      float A2, float th2) {
    float x  = up + A2;          // early
    float e1 = fmaxf(x, dg);     // early pre-reduction
    float e2 = fminf(x, dg);
    float y  = lf + A2;          // LATE
    float Mx  = fmaxf(e1, y);
    float mid = fmaxf(fminf(y, e1), e2);
    float lo  = fminf(y, e2);
    float s = ex2f_(mid - Mx) + ex2f_(lo - Mx);
    return (Mx + th2) + lg2f_(1.0f + s);
}

// 8 theta values (cols c..c+7, c even) via aligned float2, scaled to log2.
__device__ __forceinline__ void ldwin(const float* rp, int c, float* w) {
#pragma unroll
    for (int k = 0; k < 8; k += 2) {
        int cc = c + k;
        float2 v = make_float2(0.0f, 0.0f);
        if ((unsigned)cc < NDIM) v = *(const float2*)(rp + cc);
        w[k]   = v.x * L2E;
        w[k+1] = v.y * L2E;
    }
}
__device__ __forceinline__ void load4(float* W, const float* p) {
    float4 a = __ldcg((const float4*)p);
    float4 c = __ldcg((const float4*)(p + 4));
    W[0]=a.x; W[1]=a.y; W[2]=a.z; W[3]=a.w;
    W[4]=c.x; W[5]=c.y; W[6]=c.z; W[7]=c.w;
}

__global__ void __launch_bounds__(32, 1)
nw_main(const float* __restrict__ theta, const float* __restrict__ Ap,
        float* __restrict__ out) {
    const int b = blockIdx.x;
    const int t = threadIdx.x;
    const float A2 = (*Ap) * L2E;
    const int R0 = b * 64;
    const bool cons = (b > 0);

    // lane t: cell A = row R0+1+t  at col jA = s - 2t       (theta row R0+t)
    //         cell B = row R0+33+t at col jB = s - 2t - 64  (theta row R0+32+t)
    const float* thAr = theta + (size_t)(R0 + t) * NDIM;
    const float* thBr = theta + (size_t)(R0 + 32 + t) * NDIM;

    float vA1 = NEGF, vA2 = NEGF, vB1 = NEGF, vB2 = NEGF;
    float shAprev = NEGF, shBprev = NEGF, bUprev = NEGF;
    float outv = NEGF;

    float*       bout   = g_bnd[b];
    int*         myprog = &g_prog[b * 32];
    const float* bndp   = g_bnd[cons ? b - 1 : 0];
    int*         progp  = &g_prog[(cons ? b - 1 : 0) * 32];
    const int prodflag = (t == 31 && b < BKS - 1) ? 1 : 0;

    // theta windows (current + next group)
    float wAc[8], wAn[8], wBc[8], wBn[8];
    const int bA = -2 * t, bB = -2 * t - 64;
    ldwin(thAr, bA,     wAc);  ldwin(thAr, bA + 8, wAn);
    ldwin(thBr, bB,     wBc);  ldwin(thBr, bB + 8, wBn);
    float carryA = 0.0f, carryB = 0.0f;

    // boundary windows: Wc = cols 8G..8G+7 (broadcast-loaded into all lanes)
    float Wc[8], W1[8], W2[8], W3[8];
    int seen = 0;
    if (cons) {
        while ((seen = ld_acq(progp)) < 4) { }
        load4(Wc, bndp + 0);  load4(W1, bndp + 8);
        load4(W2, bndp + 16); load4(W3, bndp + 24);
    } else {
        // virtual top boundary: V[0,0]=0, else NEG
        Wc[0] = 0.0f;
#pragma unroll
        for (int k = 1; k < 8; ++k) Wc[k] = NEGF;
#pragma unroll
        for (int k = 0; k < 8; ++k) { W1[k] = NEGF; W2[k] = NEGF; W3[k] = NEGF; }
    }

    float c6 = NEGF, c7 = NEGF;   // producer chunk carry
    float pb[8];

    for (int g = 0; g < NG; ++g) {
#pragma unroll
        for (int q = 0; q < 8; ++q) {
            // shuffles read 2-step-old data -> off the critical path
            float shA = __shfl_up_sync(0xffffffffu, vA2, 1);
            float shB = __shfl_up_sync(0xffffffffu, vB2, 1);
            float s31 = __shfl_sync(0xffffffffu, vA2, 31);

            float upA = (t == 0) ? Wc[q]   : shA;
            float dgA = (t == 0) ? bUprev  : shAprev;
            float upB = (t == 0) ? s31     : shB;
            float dgB = shBprev;
            float thA = (q == 0) ? carryA : wAc[q - 1];
            float thB = (q == 0) ? carryB : wBc[q - 1];

            float nvA = lse2(upA, dgA, vA1, A2, thA);  // independent of nvB
            float nvB = lse2(upB, dgB, vB1, A2, thB);

            vA2 = vA1; vA1 = nvA;
            vB2 = vB1; vB1 = nvB;
            shAprev = shA; shBprev = upB;
            bUprev = Wc[q];
            pb[q] = nvB;
        }

        // publish chunk m = g-16 (cols 8m..8m+7 <- steps 8m+126..8m+133)
        {
            const int flag = prodflag & (int)(g >= 16);
            publish(bout + 8 * (g - 16), myprog,
                    c6, c7, pb[0], pb[1], pb[2], pb[3], pb[4], pb[5],
                    g - 15, flag);
        }
        c6 = pb[6]; c7 = pb[7];
        if (g == 271) outv = pb[6];   // V[2048,2048] at step 2174 (lane31 b31)

        // consumer ring rotate + fetch window g+4
#pragma unroll
        for (int k = 0; k < 8; ++k) { Wc[k] = W1[k]; W1[k] = W2[k]; W2[k] = W3[k]; }
        if (cons) {
            const int gd = g + 4;
            if (gd <= 256) {
                const int need = gd + 1;
                if (seen < need) {
                    do { seen = ld_acq(progp); } while (seen < need);
                }
                load4(W3, bndp + 8 * gd);
                seen = ld_acq(progp);   // pipelined refresh
            }
        }

        // theta rotate + prefetch group g+2
        carryA = wAc[7]; carryB = wBc[7];
#pragma unroll
        for (int k = 0; k < 8; ++k) { wAc[k] = wAn[k]; wBc[k] = wBn[k]; }
        if (g + 2 < NG) {
            ldwin(thAr, bA + (g + 2) * 8, wAn);
            ldwin(thBr, bB + (g + 2) * 8, wBn);
        }
    }

    if (b == BKS - 1 && t == 31) out[0] = outv * LN2;
}

extern "C" void kernel_launch(void* const* d_in, const int* in_sizes, int n_in,
                              void* d_out, int out_size) {
    const float* theta = (const float*)d_in[0];
    const float* A     = (const float*)d_in[1];
    float* out         = (float*)d_out;
    nw_init<<<1, 32>>>();
    nw_main<<<BKS, 32>>>(theta, A, out);
}

// round 7
// speedup vs baseline: 1.5497x; 1.5497x over previous
#include <cuda_runtime.h>

#define NDIM 2048
#define BKS 32                 // strips of 64 rows
#define NSTEPS 2112
#define NGROUPS 264
#define NEGF (-1.4426950e10f)  // -1e10 in log2 domain
#define L2E 1.4426950408889634f
#define LN2 0.6931471805599453f
#define BOFF 64                // col c at slot BOFF+c -> 16B-aligned v4 publishes
#define BLEN 2196

__device__ __align__(16) float g_bnd[BKS][BLEN];
__device__ int g_prog[BKS * 32];   // [b*32] = # of 8-col chunks published

__global__ void nw_init() {
    if (threadIdx.x < BKS) g_prog[threadIdx.x * 32] = 0;
}

__device__ __forceinline__ float ex2f_(float x) {
    float r; asm("ex2.approx.f32 %0, %1;" : "=f"(r) : "f"(x)); return r;
}
__device__ __forceinline__ float lg2f_(float x) {
    float r; asm("lg2.approx.f32 %0, %1;" : "=f"(r) : "f"(x)); return r;
}
__device__ __forceinline__ int ld_acq(const int* p) {
    int v; asm volatile("ld.acquire.gpu.global.b32 %0, [%1];" : "=r"(v) : "l"(p) : "memory");
    return v;
}
__device__ __forceinline__ void publish(float* dst, int* pp,
                                        float a0, float a1, float a2, float a3,
                                        float a4, float a5, float a6, float a7,
                                        int cnt, int flag) {
    asm volatile(
        "{\n\t"
        ".reg .pred p;\n\t"
        "setp.ne.s32 p, %11, 0;\n\t"
        "@p st.global.v4.f32 [%0], {%2, %3, %4, %5};\n\t"
        "@p st.global.v4.f32 [%0+16], {%6, %7, %8, %9};\n\t"
        "@p st.release.gpu.global.b32 [%1], %10;\n\t"
        "}"
        :: "l"(dst), "l"(pp),
           "f"(a0), "f"(a1), "f"(a2), "f"(a3),
           "f"(a4), "f"(a5), "f"(a6), "f"(a7),
           "r"(cnt), "r"(flag) : "memory");
}

// log2-domain smoothed max; theta passed RAW, scaled by fused FMA.
__device__ __forceinline__ float lse2(float up, float dg, float lf,
                                      float A2, float thraw) {
    float x  = up + A2;
    float y  = lf + A2;
    float w1 = fmaxf(dg, y);
    float w2 = fminf(dg, y);
    float Mx  = fmaxf(w1, x);
    float mid = fmaxf(fminf(x, w1), w2);
    float lo  = fminf(x, w2);
    float s = ex2f_(mid - Mx) + ex2f_(lo - Mx);
    return fmaf(thraw, L2E, Mx) + lg2f_(1.0f + s);
}

__global__ void __launch_bounds__(32, 1)
nw_main(const float* __restrict__ theta, const float* __restrict__ Ap,
        float* __restrict__ out) {
    // theta tile ring: 3 slots x (64 rows x 64 cols), 48KB exactly.
    // slot(w) = w % 3; tile w holds theta cols [64w, 64w+64) for this strip.
    __shared__ __align__(16) float tile[3][4096];

    const int b = blockIdx.x;
    const int t = threadIdx.x;
    const float A2 = (*Ap) * L2E;
    const int R0 = b * 64;
    const float* thbase = theta + (size_t)R0 * NDIM;

    // ---- prologue: load tile 0 into slot 0 (coalesced), zero slot 2 ----
    // (slot 2 serves negative columns during window 0: bounded values)
#pragma unroll 4
    for (int i = 0; i < 32; ++i) {
        int fq = i * 32 + t;
        int lr = fq >> 4;            // 0..63
        int cb = (fq & 15) * 4;      // 0..60
        float4 v = *(const float4*)(thbase + (size_t)lr * NDIM + cb);
        *(float4*)&tile[0][lr * 64 + cb] = v;
        *(float4*)&tile[2][lr * 64 + cb] = make_float4(0.f, 0.f, 0.f, 0.f);
    }
    __syncwarp();

    float v0m1 = NEGF, v0m2 = NEGF, v1m1 = NEGF;
    float sh_prev = NEGF;
    float bUprev = (b == 0) ? 0.0f : NEGF;   // V[R0, j0-1]; V[0,0]=0 for b==0
    float outv = NEGF;

    float*       bout   = g_bnd[b] + BOFF;
    int*         myprog = &g_prog[b * 32];
    const bool   cons   = (b > 0);
    const float* bndp   = g_bnd[cons ? b - 1 : 0] + BOFF;
    int*         progp  = &g_prog[(cons ? b - 1 : 0) * 32];
    const int prodflag = (t == 31 && b < BKS - 1) ? 1 : 0;

    // boundary consumer prologue: need chunks 0..2 (cols 1..16); 1 chunk slack
    int seen = 0;
    const int tq = t & 7;
    float bv_cur = NEGF, bv_nxt = NEGF;
    if (cons) {
        while ((seen = ld_acq(progp)) < 4) { }
        bv_cur = __ldcg(bndp + 1 + tq);
        bv_nxt = __ldcg(bndp + 9 + tq);
    }

    float c6 = NEGF, c7 = NEGF;   // producer chunk carry
    const int t2 = t << 7;        // row 2t base in tile (2t * 64)

    for (int g = 0; g < NGROUPS; ++g) {
        const int sbase = g * 8;

        // ---- tile load: during window w = g>>3, load tile w+1, rows 8k..8k+7 ----
        {
            const int wt = (g >> 3) + 1;
            if (wt <= 32) {
                const int k = g & 7;
                const int slot = wt % 3;
#pragma unroll
                for (int i = 0; i < 4; ++i) {
                    int fq = i * 32 + t;
                    int lr = 8 * k + (fq >> 4);
                    int cb = (fq & 15) * 4;
                    int gc = wt * 64 + cb;
                    float4 v = make_float4(0.f, 0.f, 0.f, 0.f);
                    if (gc < NDIM) v = *(const float4*)(thbase + (size_t)lr * NDIM + gc);
                    *(float4*)&tile[slot][lr * 64 + cb] = v;
                }
            }
            __syncwarp();
        }

        float pb[8];
#pragma unroll
        for (int q = 0; q < 8; ++q) {
            const int s = sbase + q;
            float bU = cons ? __shfl_sync(0xffffffffu, bv_cur, q) : NEGF;
            float sh = __shfl_up_sync(0xffffffffu, v1m1, 1);
            float up0 = (t == 0) ? bU : sh;
            float dg0 = (t == 0) ? bUprev : sh_prev;

            // theta from smem tile: row 2t col c0, row 2t+1 col c0-1
            const int c0  = s - 2 * t;
            const int sl0 = ((c0 + 192) >> 6) % 3;
            const int sl1 = ((c0 + 191) >> 6) % 3;
            float th0 = tile[sl0][t2 + (c0 & 63)];
            float th1 = tile[sl1][t2 + 64 + ((c0 - 1) & 63)];

            float nv0 = lse2(up0, dg0, v0m1, A2, th0);
            float nv1 = lse2(v0m1, v0m2, v1m1, A2, th1);

            v0m2 = v0m1; v0m1 = nv0;
            sh_prev = sh; bUprev = bU;
            v1m1 = nv1;
            pb[q] = nv1;
            if (s == 2110) outv = nv1;   // V[2048,2048] (lane31 of block31)
        }

        // publish chunk m = g-8 (cols 8m..8m+7 <- steps 8m+62..8m+69), cnt = m+1
        {
            const int flag = prodflag & (int)(g >= 8);
            publish(bout + 8 * (g - 8), myprog,
                    c6, c7, pb[0], pb[1], pb[2], pb[3], pb[4], pb[5],
                    g - 7, flag);
        }
        c6 = pb[6]; c7 = pb[7];

        // consumer: rotate double buffer; next window cols 8g+17..8g+24 are in
        // chunks g+2..g+3 -> need cnt >= g+4
        if (cons) {
            bv_cur = bv_nxt;
            const int nbase = sbase + 16;
            if (nbase < NSTEPS) {
                const int gneed = min(g + 4, 257);
                if (seen < gneed) {
                    do { seen = ld_acq(progp); } while (seen < gneed);
                }
                bv_nxt = __ldcg(bndp + nbase + 1 + tq);
            }
        }
    }

    // epilogue: final chunk 256 covers col 2048 (= c6); counter past all needs
    publish(bout + 2048, myprog, c6, c7, c7, c7, c7, c7, c7, c7, 280, prodflag);

    if (b == BKS - 1 && t == 31) out[0] = outv * LN2;
}

extern "C" void kernel_launch(void* const* d_in, const int* in_sizes, int n_in,
                              void* d_out, int out_size) {
    const float* theta = (const float*)d_in[0];
    const float* A     = (const float*)d_in[1];
    float* out         = (float*)d_out;
    nw_init<<<1, 32>>>();
    nw_main<<<BKS, 32>>>(theta, A, out);
}